// round 3
// baseline (speedup 1.0000x reference)
#include <cuda_runtime.h>
#include <cuda_fp16.h>
#include <cstdint>

// Problem constants
#define IM_PIX   16384      // 128*128 pixels
#define BC       32         // 2*16 maps
#define HT_BINS  33120      // 184*180
#define N_VOTES  4000000
#define INV_NORM (1.0f/128.0f)
#define CAP      256        // per-bin bucket capacity (Poisson mean 121, 12-sigma safe)

// Scratch (__device__ globals; allocation-free rule)
__device__ __half g_xTh[IM_PIX * BC];          // pixel-major fp16 gather table, 1 MB
__device__ float  g_acc[HT_BINS * BC];         // overflow-fallback accumulator, 4.24 MB
__device__ int    g_cnt[HT_BINS];              // per-bin vote counts
__device__ uint2  g_bucket[(size_t)HT_BINS * CAP];  // {pixel, weight_bits}, 67.8 MB

// ---------------------------------------------------------------------------
// Zero counters + fallback accumulator
// ---------------------------------------------------------------------------
__global__ void zero_kernel() {
    int i = blockIdx.x * blockDim.x + threadIdx.x;
    if (i < (HT_BINS * BC) / 4)
        reinterpret_cast<float4*>(g_acc)[i] = make_float4(0.f, 0.f, 0.f, 0.f);
    if (i < HT_BINS)
        g_cnt[i] = 0;
}

// ---------------------------------------------------------------------------
// Transpose x [BC, IM_PIX] fp32 -> g_xTh [IM_PIX, BC] fp16, tiled via smem
// ---------------------------------------------------------------------------
__global__ void transpose_x_kernel(const float* __restrict__ x) {
    __shared__ float tile[32][64 + 1];
    int p0 = blockIdx.x * 64;
    int t  = threadIdx.x;
    #pragma unroll
    for (int i = 0; i < 8; i++) {
        int idx = t + i * 256;          // idx = m*64 + pl
        int m  = idx >> 6;
        int pl = idx & 63;
        tile[m][pl] = x[(size_t)m * IM_PIX + p0 + pl];
    }
    __syncthreads();
    #pragma unroll
    for (int i = 0; i < 8; i++) {
        int idx = t + i * 256;          // idx = pl*32 + m
        int pl = idx >> 5;
        int m  = idx & 31;
        g_xTh[(size_t)(p0 + pl) * BC + m] = __float2half(tile[m][pl]);
    }
}

// ---------------------------------------------------------------------------
// Scatter votes into per-bin buckets. One thread per vote.
// 4M spread-address counter atomics (cheap) + one 8B payload write.
// Overflow (never in practice): correct fallback via global fp32 atomics.
// ---------------------------------------------------------------------------
__global__ void scatter_kernel(const int*   __restrict__ vp,
                               const int*   __restrict__ vb,
                               const float* __restrict__ vw) {
    int v = blockIdx.x * blockDim.x + threadIdx.x;
    if (v >= N_VOTES) return;
    int   p = vp[v];
    int   b = vb[v];
    float w = vw[v];
    int pos = atomicAdd(&g_cnt[b], 1);
    if (pos < CAP) {
        g_bucket[(size_t)b * CAP + pos] = make_uint2((unsigned)p, __float_as_uint(w));
    } else {
        float*        dst = g_acc + (size_t)b * BC;
        const __half* src = g_xTh + (size_t)p * BC;
        #pragma unroll
        for (int m = 0; m < BC; m++)
            atomicAdd(dst + m, __half2float(src[m]) * w);
    }
}

// ---------------------------------------------------------------------------
// Accumulate: one warp per bin, zero atomics.
//   half = lane>>4 selects one of 2 votes processed per step;
//   sub  = lane&15 selects the map pair (2*sub, 2*sub+1) -> one LDG.U32
//   serves 2 fp16 map values, so one warp-LDG covers 2 votes x 32 maps.
// Final: halves combined via shfl_xor(16); lanes 0-15 write out directly.
// ---------------------------------------------------------------------------
__global__ void accum_kernel(float* __restrict__ out) {
    int warp = (blockIdx.x * blockDim.x + threadIdx.x) >> 5;
    int lane = threadIdx.x & 31;
    if (warp >= HT_BINS) return;
    int b    = warp;
    int half = lane >> 4;
    int sub  = lane & 15;

    int n = g_cnt[b];
    if (n > CAP) n = CAP;

    float2 acc = make_float2(0.f, 0.f);
    if (half == 0) {   // fold in the (normally zero) overflow accumulator once
        acc = *(reinterpret_cast<const float2*>(g_acc + (size_t)b * BC) + sub);
    }

    const uint2* bucket = g_bucket + (size_t)b * CAP;
    for (int base = 0; base < n; base += 32) {
        int   idx = base + lane;
        uint2 pk  = (idx < n) ? bucket[idx] : make_uint2(0u, 0u);  // w=0 pad
        #pragma unroll
        for (int s = 0; s < 32; s += 2) {
            if (base + s >= n) break;                  // warp-uniform
            int src  = s + half;                       // my half-warp's vote slot
            unsigned pu = __shfl_sync(0xffffffffu, pk.x, src);
            unsigned wu = __shfl_sync(0xffffffffu, pk.y, src);
            float w = __uint_as_float(wu);
            __half2 h = *(reinterpret_cast<const __half2*>(g_xTh + (size_t)pu * BC) + sub);
            float2  f = __half22float2(h);
            acc.x += f.x * w;
            acc.y += f.y * w;
        }
    }

    // combine the two half-warps' partial sums
    acc.x += __shfl_xor_sync(0xffffffffu, acc.x, 16);
    acc.y += __shfl_xor_sync(0xffffffffu, acc.y, 16);

    if (half == 0) {
        out[(size_t)(2 * sub)     * HT_BINS + b] = acc.x * INV_NORM;
        out[(size_t)(2 * sub + 1) * HT_BINS + b] = acc.y * INV_NORM;
    }
}

// ---------------------------------------------------------------------------
// Launch pipeline (all async, graph-capturable)
// ---------------------------------------------------------------------------
extern "C" void kernel_launch(void* const* d_in, const int* in_sizes, int n_in,
                              void* d_out, int out_size) {
    const float* x  = (const float*)d_in[0];   // [2,16,128,128] fp32
    const int*   vp = (const int*)  d_in[1];   // vote_pixel  [4M]
    const int*   vb = (const int*)  d_in[2];   // vote_bin    [4M]
    const float* vw = (const float*)d_in[3];   // vote_weight [4M]
    float* out = (float*)d_out;                // [2,16,184,180] fp32

    const int TB = 256;

    zero_kernel       <<<((HT_BINS * BC / 4) + TB - 1) / TB, TB>>>();
    transpose_x_kernel<<<IM_PIX / 64, TB>>>(x);
    scatter_kernel    <<<(N_VOTES + TB - 1) / TB, TB>>>(vp, vb, vw);

    int warps_needed = HT_BINS;
    int blocks = (warps_needed * 32 + TB - 1) / TB;
    accum_kernel<<<blocks, TB>>>(out);
}